// round 7
// baseline (speedup 1.0000x reference)
#include <cuda_runtime.h>
#include <cuda_fp16.h>
#include <mma.h>
#include <cstdint>

using namespace nvcuda;

// GraphConvolution: y = A @ (x @ W^T) + b
//   x: (B=4, N=50000, C=128) f32, adj: (2, E=800000) i32, vals: (E,) f32
//   W: (128,128) f32, b: (128,) f32, out: (B,N,128) f32

#define C_DIM 128
#define B_DIM 4
#define N_ROWS 50000
#define E_MAX  800000

// z stored fp16, node-major: z_h[n][b][c] -> 128 uint2 (512 halfs) per node.
__device__ uint2  g_zh[(size_t)N_ROWS * 128];
__device__ int    g_cnt[N_ROWS];
__device__ int    g_rowptr[N_ROWS + 1];
__device__ int    g_ofs[N_ROWS];
__device__ float2 g_edata[E_MAX];

// ===========================================================================
// Persistent GEMM z = x @ W^T (wmma tf32), fp16 node-major output.
// One CTA per SM loops over 128-row tiles. W staged to smem ONCE per CTA.
// A tiles double-buffered: LDG of next tile issued before computing current.
// smem: Ws[128][LDA] + A0[128][LDA] + A1[128][LDA] = 208896 B.
// ===========================================================================
#define LDA 136
#define LDO 132
#define GEMM_SMEM (3 * 128 * LDA * 4)

__global__ __launch_bounds__(256, 1)
void gemm_persist(const float* __restrict__ x, const float* __restrict__ W,
                  int M, int N, int numTiles) {
    extern __shared__ float smem[];
    float* Ws = smem;                    // [128][LDA]
    float* A0 = smem + 128 * LDA;
    float* A1 = A0 + 128 * LDA;

    const int tid = threadIdx.x;
    const int wid = tid >> 5;
    const int wm = wid & 1;
    const int wn = wid >> 1;

    // Stage W once (rna tf32 conversion).
    #pragma unroll
    for (int it = 0; it < 16; it++) {
        int idx = tid + it * 256;
        int row = idx >> 5;
        int kq  = idx & 31;
        float4 v = *(const float4*)(W + row * C_DIM + kq * 4);
        v.x = wmma::__float_to_tf32(v.x); v.y = wmma::__float_to_tf32(v.y);
        v.z = wmma::__float_to_tf32(v.z); v.w = wmma::__float_to_tf32(v.w);
        *(float4*)(Ws + row * LDA + kq * 4) = v;
    }

    int t = blockIdx.x;
    float4 r[16];

    // Prologue: load first tile's A into registers.
    if (t < numTiles) {
        long long m0 = (long long)t * 128;
        #pragma unroll
        for (int it = 0; it < 16; it++) {
            int idx = tid + it * 256;
            int row = idx >> 5;
            int kq  = idx & 31;
            long long gm = m0 + row; if (gm >= M) gm = M - 1;
            r[it] = __ldcs((const float4*)(x + gm * C_DIM + kq * 4));
        }
    }
    __syncthreads();   // Ws ready

    int cur = 0;
    while (t < numTiles) {
        float* As = cur ? A1 : A0;
        float* Ao = cur ? A0 : A1;
        const long long m0 = (long long)t * 128;

        // Convert + STS current tile.
        #pragma unroll
        for (int it = 0; it < 16; it++) {
            int idx = tid + it * 256;
            int row = idx >> 5;
            int kq  = idx & 31;
            float4 v = r[it];
            v.x = wmma::__float_to_tf32(v.x); v.y = wmma::__float_to_tf32(v.y);
            v.z = wmma::__float_to_tf32(v.z); v.w = wmma::__float_to_tf32(v.w);
            *(float4*)(As + row * LDA + kq * 4) = v;
        }
        __syncthreads();

        // Kick off next tile's loads (overlapped with compute below).
        const int tn = t + gridDim.x;
        if (tn < numTiles) {
            long long m1 = (long long)tn * 128;
            #pragma unroll
            for (int it = 0; it < 16; it++) {
                int idx = tid + it * 256;
                int row = idx >> 5;
                int kq  = idx & 31;
                long long gm = m1 + row; if (gm >= M) gm = M - 1;
                r[it] = __ldcs((const float4*)(x + gm * C_DIM + kq * 4));
            }
        }

        // Compute 128x128 tile.
        wmma::fragment<wmma::accumulator, 16, 16, 8, float> acc[4][2];
        #pragma unroll
        for (int i = 0; i < 4; i++)
            #pragma unroll
            for (int j = 0; j < 2; j++) wmma::fill_fragment(acc[i][j], 0.0f);

        #pragma unroll
        for (int ks = 0; ks < 16; ks++) {
            const int k = ks * 8;
            wmma::fragment<wmma::matrix_a, 16, 16, 8, wmma::precision::tf32,
                           wmma::row_major> a[4];
            wmma::fragment<wmma::matrix_b, 16, 16, 8, wmma::precision::tf32,
                           wmma::col_major> b[2];
            #pragma unroll
            for (int i = 0; i < 4; i++)
                wmma::load_matrix_sync(a[i], As + (wm * 64 + i * 16) * LDA + k, LDA);
            #pragma unroll
            for (int j = 0; j < 2; j++)
                wmma::load_matrix_sync(b[j], Ws + (wn * 32 + j * 16) * LDA + k, LDA);
            #pragma unroll
            for (int i = 0; i < 4; i++)
                #pragma unroll
                for (int j = 0; j < 2; j++)
                    wmma::mma_sync(acc[i][j], a[i], b[j], acc[i][j]);
        }

        // Epilogue: frags -> Ao (stride LDO) -> fp16 node-major z.
        #pragma unroll
        for (int i = 0; i < 4; i++)
            #pragma unroll
            for (int j = 0; j < 2; j++)
                wmma::store_matrix_sync(
                    Ao + (wm * 64 + i * 16) * LDO + wn * 32 + j * 16,
                    acc[i][j], LDO, wmma::mem_row_major);
        __syncthreads();

        #pragma unroll
        for (int it = 0; it < 16; it++) {
            int idx = tid + it * 256;
            int row = idx >> 5;
            int q   = idx & 31;
            long long gm = m0 + row;
            if (gm < M) {
                float4 v = *(const float4*)(Ao + row * LDO + q * 4);
                __half2 h0 = __floats2half2_rn(v.x, v.y);
                __half2 h1 = __floats2half2_rn(v.z, v.w);
                int b = (int)(gm / N);
                int n = (int)(gm % N);
                uint2 pack;
                pack.x = *(uint32_t*)&h0;
                pack.y = *(uint32_t*)&h1;
                g_zh[(size_t)n * 128 + b * 32 + q] = pack;
            }
        }
        __syncthreads();   // Ao reads done before it becomes next STS target

        cur ^= 1;
        t = tn;
    }
}

// ===========================================================================
// CSR build
// ===========================================================================
__global__ void k_zero_cnt(int n) {
    int i = blockIdx.x * blockDim.x + threadIdx.x;
    if (i < n) g_cnt[i] = 0;
}

__global__ void k_count(const int* __restrict__ rows, int E) {
    int e = blockIdx.x * blockDim.x + threadIdx.x;
    if (e < E) atomicAdd(&g_cnt[rows[e]], 1);
}

#define SCAN_T 1024
__global__ __launch_bounds__(SCAN_T)
void k_scan(int n, int E) {
    __shared__ int s[SCAN_T];
    const int t = threadIdx.x;
    const int chunk = (n + SCAN_T - 1) / SCAN_T;
    const int base = t * chunk;
    int sum = 0;
    for (int j = 0; j < chunk; j++) {
        int r = base + j;
        if (r < n) sum += g_cnt[r];
    }
    s[t] = sum;
    __syncthreads();
    #pragma unroll
    for (int d = 1; d < SCAN_T; d <<= 1) {
        int v = (t >= d) ? s[t - d] : 0;
        __syncthreads();
        s[t] += v;
        __syncthreads();
    }
    int run = s[t] - sum;
    for (int j = 0; j < chunk; j++) {
        int r = base + j;
        if (r < n) {
            g_rowptr[r] = run;
            g_ofs[r]    = run;
            run += g_cnt[r];
        }
    }
    if (t == 0) g_rowptr[n] = E;
}

__global__ void k_fill(const int* __restrict__ rows, const int* __restrict__ cols,
                       const float* __restrict__ vals, int E) {
    int e = blockIdx.x * blockDim.x + threadIdx.x;
    if (e >= E) return;
    int r = rows[e];
    int pos = atomicAdd(&g_ofs[r], 1);
    float2 ed;
    ed.x = __int_as_float(cols[e]);
    ed.y = vals[e];
    g_edata[pos] = ed;
}

// ===========================================================================
// Gather: 2 warps per row; each warp covers 2 batches (512B per edge).
// fp32 accumulate, bias fused, streaming stores.
// ===========================================================================
__device__ __forceinline__ void accum_pair(const uint2* __restrict__ src,
                                           int lane, float v,
                                           float4& a0, float4& a1) {
    uint2 p0 = __ldg(src + lane);
    uint2 p1 = __ldg(src + lane + 32);
    float2 fa, fb;
    fa = __half22float2(*(__half2*)&p0.x); fb = __half22float2(*(__half2*)&p0.y);
    a0.x = fmaf(v, fa.x, a0.x); a0.y = fmaf(v, fa.y, a0.y);
    a0.z = fmaf(v, fb.x, a0.z); a0.w = fmaf(v, fb.y, a0.w);
    fa = __half22float2(*(__half2*)&p1.x); fb = __half22float2(*(__half2*)&p1.y);
    a1.x = fmaf(v, fa.x, a1.x); a1.y = fmaf(v, fa.y, a1.y);
    a1.z = fmaf(v, fb.x, a1.z); a1.w = fmaf(v, fb.y, a1.w);
}

__global__ __launch_bounds__(256)
void k_gather(const float* __restrict__ bias, float* __restrict__ out, int N) {
    int gw   = (blockIdx.x * blockDim.x + threadIdx.x) >> 5;
    int lane = threadIdx.x & 31;
    int r    = gw >> 1;
    int half = gw & 1;          // 0: batches {0,1}, 1: batches {2,3}
    if (r >= N) return;
    const int boff = half * 64; // uint2 offset into node block

    float4 acc0 = make_float4(0.f, 0.f, 0.f, 0.f);
    float4 acc1 = acc0, bcc0 = acc0, bcc1 = acc0;

    const int start = g_rowptr[r];
    const int end   = g_rowptr[r + 1];

    int i = start;
    for (; i + 2 <= end; i += 2) {
        float2 e0 = __ldg(&g_edata[i]);
        float2 e1 = __ldg(&g_edata[i + 1]);
        const uint2* s0 = g_zh + (size_t)__float_as_int(e0.x) * 128 + boff;
        const uint2* s1 = g_zh + (size_t)__float_as_int(e1.x) * 128 + boff;
        accum_pair(s0, lane, e0.y, acc0, acc1);
        accum_pair(s1, lane, e1.y, bcc0, bcc1);
    }
    if (i < end) {
        float2 e0 = __ldg(&g_edata[i]);
        const uint2* s0 = g_zh + (size_t)__float_as_int(e0.x) * 128 + boff;
        accum_pair(s0, lane, e0.y, acc0, acc1);
    }

    float4 bv = ((const float4*)bias)[lane];
    acc0.x += bcc0.x + bv.x; acc0.y += bcc0.y + bv.y;
    acc0.z += bcc0.z + bv.z; acc0.w += bcc0.w + bv.w;
    acc1.x += bcc1.x + bv.x; acc1.y += bcc1.y + bv.y;
    acc1.z += bcc1.z + bv.z; acc1.w += bcc1.w + bv.w;

    const size_t NB = (size_t)N * 32;   // float4 units per batch
    float4* dst = (float4*)out + (size_t)(half * 2) * NB + (size_t)r * 32 + lane;
    __stcs(dst,      acc0);
    __stcs(dst + NB, acc1);
}

// ===========================================================================
extern "C" void kernel_launch(void* const* d_in, const int* in_sizes, int n_in,
                              void* d_out, int out_size) {
    const float* x    = (const float*)d_in[0];
    const int*   adj  = (const int*)d_in[1];
    const float* vals = (const float*)d_in[2];
    const float* W    = (const float*)d_in[3];
    const float* bias = (const float*)d_in[4];
    float* out = (float*)d_out;

    const int E = in_sizes[2];
    const int N = in_sizes[0] / (B_DIM * C_DIM);
    const int M = B_DIM * N;

    const int* rows = adj;
    const int* cols = adj + E;

    static cudaStream_t s2 = nullptr;
    static cudaEvent_t evFork, evJoin;
    static int nsm = 0;
    if (!s2) {
        cudaStreamCreateWithFlags(&s2, cudaStreamNonBlocking);
        cudaEventCreateWithFlags(&evFork, cudaEventDisableTiming);
        cudaEventCreateWithFlags(&evJoin, cudaEventDisableTiming);
        cudaDeviceGetAttribute(&nsm, cudaDevAttrMultiProcessorCount, 0);
        cudaFuncSetAttribute(gemm_persist,
                             cudaFuncAttributeMaxDynamicSharedMemorySize, GEMM_SMEM);
    }

    // Fork: CSR build on s2, GEMM on default stream (independent data).
    cudaEventRecord(evFork, 0);
    cudaStreamWaitEvent(s2, evFork, 0);

    k_zero_cnt<<<(N + 255) / 256, 256, 0, s2>>>(N);
    k_count<<<(E + 255) / 256, 256, 0, s2>>>(rows, E);
    k_scan<<<1, SCAN_T, 0, s2>>>(N, E);
    k_fill<<<(E + 255) / 256, 256, 0, s2>>>(rows, cols, vals, E);
    cudaEventRecord(evJoin, s2);

    const int numTiles = (M + 127) / 128;
    int grid = nsm < numTiles ? nsm : numTiles;
    gemm_persist<<<grid, 256, GEMM_SMEM>>>(x, W, M, N, numTiles);

    // Join: gather needs both CSR and z.
    cudaStreamWaitEvent(0, evJoin, 0);
    int blocks = (N * 64 + 255) / 256;
    k_gather<<<blocks, 256>>>(bias, out, N);
}

// round 8
// speedup vs baseline: 1.1479x; 1.1479x over previous
#include <cuda_runtime.h>
#include <cuda_fp16.h>
#include <mma.h>
#include <cstdint>

using namespace nvcuda;

// GraphConvolution: y = A @ (x @ W^T) + b
//   x: (B=4, N=50000, C=128) f32, adj: (2, E=800000) i32, vals: (E,) f32
//   W: (128,128) f32, b: (128,) f32, out: (B,N,128) f32

#define C_DIM 128
#define B_DIM 4
#define N_ROWS 50000
#define E_MAX  800000

// z stored fp16, node-major: z_h[n][b][c] -> 128 uint2 (512 halfs) per node.
__device__ uint2  g_zh[(size_t)N_ROWS * 128];
__device__ int    g_cnt[N_ROWS];
__device__ int    g_rowptr[N_ROWS + 1];
__device__ int    g_ofs[N_ROWS];
__device__ float2 g_edata[E_MAX];

// ===========================================================================
// GEMM z = x @ W^T via wmma tf32 (m16n16k8), output fp16 node-major.
// CTA tile: 128(m) x 128(n) x 128(k). 8 warps 2x4; each 64x32 (4x2 frags).
// (exact R6 version — known-good ~80us)
// ===========================================================================
#define LDA 136
#define LDO 132
#define GEMM_SMEM (2 * 128 * LDA * 4)   // 139264 bytes

__global__ __launch_bounds__(256, 1)
void gemm_wmma(const float* __restrict__ x, const float* __restrict__ W,
               int M, int N) {
    extern __shared__ float smem[];
    float* As = smem;               // [128][LDA]
    float* Bs = smem + 128 * LDA;   // [128][LDA]

    const int tid = threadIdx.x;
    const int wid = tid >> 5;
    const long long m0 = (long long)blockIdx.x * 128;

    #pragma unroll
    for (int it = 0; it < 16; it++) {
        int idx = tid + it * 256;
        int row = idx >> 5;
        int kq  = idx & 31;
        long long gm = m0 + row; if (gm >= M) gm = M - 1;
        float4 v = __ldcs((const float4*)(x + gm * C_DIM + kq * 4));
        v.x = wmma::__float_to_tf32(v.x); v.y = wmma::__float_to_tf32(v.y);
        v.z = wmma::__float_to_tf32(v.z); v.w = wmma::__float_to_tf32(v.w);
        *(float4*)(As + row * LDA + kq * 4) = v;
    }
    #pragma unroll
    for (int it = 0; it < 16; it++) {
        int idx = tid + it * 256;
        int row = idx >> 5;
        int kq  = idx & 31;
        float4 v = *(const float4*)(W + row * C_DIM + kq * 4);
        v.x = wmma::__float_to_tf32(v.x); v.y = wmma::__float_to_tf32(v.y);
        v.z = wmma::__float_to_tf32(v.z); v.w = wmma::__float_to_tf32(v.w);
        *(float4*)(Bs + row * LDA + kq * 4) = v;
    }
    __syncthreads();

    const int wm = wid & 1;
    const int wn = wid >> 1;

    wmma::fragment<wmma::accumulator, 16, 16, 8, float> acc[4][2];
    #pragma unroll
    for (int i = 0; i < 4; i++)
        #pragma unroll
        for (int j = 0; j < 2; j++) wmma::fill_fragment(acc[i][j], 0.0f);

    #pragma unroll
    for (int ks = 0; ks < 16; ks++) {
        const int k = ks * 8;
        wmma::fragment<wmma::matrix_a, 16, 16, 8, wmma::precision::tf32,
                       wmma::row_major> a[4];
        wmma::fragment<wmma::matrix_b, 16, 16, 8, wmma::precision::tf32,
                       wmma::col_major> b[2];
        #pragma unroll
        for (int i = 0; i < 4; i++)
            wmma::load_matrix_sync(a[i], As + (wm * 64 + i * 16) * LDA + k, LDA);
        #pragma unroll
        for (int j = 0; j < 2; j++)
            wmma::load_matrix_sync(b[j], Bs + (wn * 32 + j * 16) * LDA + k, LDA);
        #pragma unroll
        for (int i = 0; i < 4; i++)
            #pragma unroll
            for (int j = 0; j < 2; j++)
                wmma::mma_sync(acc[i][j], a[i], b[j], acc[i][j]);
    }

    // Epilogue: frags -> smem -> fp16 node-major z (write-back: wants L2).
    __syncthreads();
    float* Os = smem;
    #pragma unroll
    for (int i = 0; i < 4; i++)
        #pragma unroll
        for (int j = 0; j < 2; j++)
            wmma::store_matrix_sync(
                Os + (wm * 64 + i * 16) * LDO + wn * 32 + j * 16,
                acc[i][j], LDO, wmma::mem_row_major);
    __syncthreads();

    #pragma unroll
    for (int it = 0; it < 16; it++) {
        int idx = tid + it * 256;
        int row = idx >> 5;
        int q   = idx & 31;
        long long gm = m0 + row;
        if (gm < M) {
            float4 v = *(const float4*)(Os + row * LDO + q * 4);
            __half2 h0 = __floats2half2_rn(v.x, v.y);
            __half2 h1 = __floats2half2_rn(v.z, v.w);
            int b = (int)(gm / N);
            int n = (int)(gm % N);
            uint2 pack;
            pack.x = *(uint32_t*)&h0;
            pack.y = *(uint32_t*)&h1;
            g_zh[(size_t)n * 128 + b * 32 + q] = pack;
        }
    }
}

// ===========================================================================
// CSR build
// ===========================================================================
__global__ void k_zero_cnt(int n) {
    int i = blockIdx.x * blockDim.x + threadIdx.x;
    if (i < n) g_cnt[i] = 0;
}

__global__ void k_count(const int* __restrict__ rows, int E) {
    int e = blockIdx.x * blockDim.x + threadIdx.x;
    if (e < E) atomicAdd(&g_cnt[rows[e]], 1);
}

#define SCAN_T 1024
__global__ __launch_bounds__(SCAN_T)
void k_scan(int n, int E) {
    __shared__ int s[SCAN_T];
    const int t = threadIdx.x;
    const int chunk = (n + SCAN_T - 1) / SCAN_T;
    const int base = t * chunk;
    int sum = 0;
    for (int j = 0; j < chunk; j++) {
        int r = base + j;
        if (r < n) sum += g_cnt[r];
    }
    s[t] = sum;
    __syncthreads();
    #pragma unroll
    for (int d = 1; d < SCAN_T; d <<= 1) {
        int v = (t >= d) ? s[t - d] : 0;
        __syncthreads();
        s[t] += v;
        __syncthreads();
    }
    int run = s[t] - sum;
    for (int j = 0; j < chunk; j++) {
        int r = base + j;
        if (r < n) {
            g_rowptr[r] = run;
            g_ofs[r]    = run;
            run += g_cnt[r];
        }
    }
    if (t == 0) g_rowptr[n] = E;
}

__global__ void k_fill(const int* __restrict__ rows, const int* __restrict__ cols,
                       const float* __restrict__ vals, int E) {
    int e = blockIdx.x * blockDim.x + threadIdx.x;
    if (e >= E) return;
    int r = rows[e];
    int pos = atomicAdd(&g_ofs[r], 1);
    float2 ed;
    ed.x = __int_as_float(cols[e]);
    ed.y = vals[e];
    g_edata[pos] = ed;
}

// ===========================================================================
// Gather (exact R6 version): one warp per row, 2-way unrolled edge loop,
// fp32 accumulation, bias fused, streaming stores.
// ===========================================================================
__device__ __forceinline__ void accum_node(const uint2* __restrict__ src,
                                           int lane, float v,
                                           float4& a0, float4& a1,
                                           float4& a2, float4& a3) {
    uint2 p0 = __ldg(src + lane);
    uint2 p1 = __ldg(src + lane + 32);
    uint2 p2 = __ldg(src + lane + 64);
    uint2 p3 = __ldg(src + lane + 96);
    float2 fa, fb;
    fa = __half22float2(*(__half2*)&p0.x); fb = __half22float2(*(__half2*)&p0.y);
    a0.x = fmaf(v, fa.x, a0.x); a0.y = fmaf(v, fa.y, a0.y);
    a0.z = fmaf(v, fb.x, a0.z); a0.w = fmaf(v, fb.y, a0.w);
    fa = __half22float2(*(__half2*)&p1.x); fb = __half22float2(*(__half2*)&p1.y);
    a1.x = fmaf(v, fa.x, a1.x); a1.y = fmaf(v, fa.y, a1.y);
    a1.z = fmaf(v, fb.x, a1.z); a1.w = fmaf(v, fb.y, a1.w);
    fa = __half22float2(*(__half2*)&p2.x); fb = __half22float2(*(__half2*)&p2.y);
    a2.x = fmaf(v, fa.x, a2.x); a2.y = fmaf(v, fa.y, a2.y);
    a2.z = fmaf(v, fb.x, a2.z); a2.w = fmaf(v, fb.y, a2.w);
    fa = __half22float2(*(__half2*)&p3.x); fb = __half22float2(*(__half2*)&p3.y);
    a3.x = fmaf(v, fa.x, a3.x); a3.y = fmaf(v, fa.y, a3.y);
    a3.z = fmaf(v, fb.x, a3.z); a3.w = fmaf(v, fb.y, a3.w);
}

__global__ __launch_bounds__(256)
void k_gather(const float* __restrict__ bias, float* __restrict__ out, int N) {
    int gw   = (blockIdx.x * blockDim.x + threadIdx.x) >> 5;
    int lane = threadIdx.x & 31;
    if (gw >= N) return;
    const int r = gw;

    float4 acc0 = make_float4(0.f, 0.f, 0.f, 0.f);
    float4 acc1 = acc0, acc2 = acc0, acc3 = acc0;
    float4 bcc0 = acc0, bcc1 = acc0, bcc2 = acc0, bcc3 = acc0;

    const int start = g_rowptr[r];
    const int end   = g_rowptr[r + 1];

    int i = start;
    for (; i + 2 <= end; i += 2) {
        float2 e0 = __ldg(&g_edata[i]);
        float2 e1 = __ldg(&g_edata[i + 1]);
        const uint2* s0 = g_zh + (size_t)__float_as_int(e0.x) * 128;
        const uint2* s1 = g_zh + (size_t)__float_as_int(e1.x) * 128;
        accum_node(s0, lane, e0.y, acc0, acc1, acc2, acc3);
        accum_node(s1, lane, e1.y, bcc0, bcc1, bcc2, bcc3);
    }
    if (i < end) {
        float2 e0 = __ldg(&g_edata[i]);
        const uint2* s0 = g_zh + (size_t)__float_as_int(e0.x) * 128;
        accum_node(s0, lane, e0.y, acc0, acc1, acc2, acc3);
    }

    float4 bv = ((const float4*)bias)[lane];
    acc0.x += bcc0.x + bv.x; acc0.y += bcc0.y + bv.y;
    acc0.z += bcc0.z + bv.z; acc0.w += bcc0.w + bv.w;
    acc1.x += bcc1.x + bv.x; acc1.y += bcc1.y + bv.y;
    acc1.z += bcc1.z + bv.z; acc1.w += bcc1.w + bv.w;
    acc2.x += bcc2.x + bv.x; acc2.y += bcc2.y + bv.y;
    acc2.z += bcc2.z + bv.z; acc2.w += bcc2.w + bv.w;
    acc3.x += bcc3.x + bv.x; acc3.y += bcc3.y + bv.y;
    acc3.z += bcc3.z + bv.z; acc3.w += bcc3.w + bv.w;

    const size_t NB = (size_t)N * 32;   // float4 units per batch
    float4* dst = (float4*)out + (size_t)r * 32 + lane;
    __stcs(dst,          acc0);
    __stcs(dst + NB,     acc1);
    __stcs(dst + 2 * NB, acc2);
    __stcs(dst + 3 * NB, acc3);
}

// ===========================================================================
extern "C" void kernel_launch(void* const* d_in, const int* in_sizes, int n_in,
                              void* d_out, int out_size) {
    const float* x    = (const float*)d_in[0];
    const int*   adj  = (const int*)d_in[1];
    const float* vals = (const float*)d_in[2];
    const float* W    = (const float*)d_in[3];
    const float* bias = (const float*)d_in[4];
    float* out = (float*)d_out;

    const int E = in_sizes[2];
    const int N = in_sizes[0] / (B_DIM * C_DIM);
    const int M = B_DIM * N;

    const int* rows = adj;
    const int* cols = adj + E;

    static cudaStream_t s2 = nullptr;
    static cudaEvent_t evFork, evJoin;
    if (!s2) {
        cudaStreamCreateWithFlags(&s2, cudaStreamNonBlocking);
        cudaEventCreateWithFlags(&evFork, cudaEventDisableTiming);
        cudaEventCreateWithFlags(&evJoin, cudaEventDisableTiming);
        cudaFuncSetAttribute(gemm_wmma,
                             cudaFuncAttributeMaxDynamicSharedMemorySize, GEMM_SMEM);
    }

    // Fork: CSR build on s2 runs concurrently with GEMM on the main stream.
    cudaEventRecord(evFork, 0);
    cudaStreamWaitEvent(s2, evFork, 0);

    k_zero_cnt<<<(N + 255) / 256, 256, 0, s2>>>(N);
    k_count<<<(E + 255) / 256, 256, 0, s2>>>(rows, E);
    k_scan<<<1, SCAN_T, 0, s2>>>(N, E);
    k_fill<<<(E + 255) / 256, 256, 0, s2>>>(rows, cols, vals, E);
    cudaEventRecord(evJoin, s2);

    // GEMM (R6 version)
    int gtiles = (M + 127) / 128;
    gemm_wmma<<<gtiles, 256, GEMM_SMEM>>>(x, W, M, N);

    // Join: gather needs both CSR and z.
    cudaStreamWaitEvent(0, evJoin, 0);
    int blocks = (N * 32 + 255) / 256;
    k_gather<<<blocks, 256>>>(bias, out, N);
}

// round 9
// speedup vs baseline: 1.2133x; 1.0570x over previous
#include <cuda_runtime.h>
#include <cuda_fp16.h>
#include <mma.h>
#include <cstdint>

using namespace nvcuda;

// GraphConvolution: y = A @ (x @ W^T) + b
//   x: (B=4, N=50000, C=128) f32, adj: (2, E=800000) i32, vals: (E,) f32
//   W: (128,128) f32, b: (128,) f32, out: (B,N,128) f32

#define C_DIM 128
#define B_DIM 4
#define N_ROWS 50000
#define E_MAX  800000

// z stored fp16, node-major: z_h[n][b][c] -> 128 uint2 (512 halfs) per node.
__device__ uint2  g_zh[(size_t)N_ROWS * 128];
__device__ int    g_cnt[N_ROWS];
__device__ int    g_rowptr[N_ROWS + 1];
__device__ int    g_ofs[N_ROWS];
__device__ float2 g_edata[E_MAX];

// ===========================================================================
// GEMM z = x @ W^T via wmma tf32 (m16n16k8), output fp16 node-major.
// CTA tile: 128(m) x 128(n) x 128(k). 8 warps 2x4; each 64x32 (4x2 frags).
// (exact R6/R8 version — known-good)
// ===========================================================================
#define LDA 136
#define LDO 132
#define GEMM_SMEM (2 * 128 * LDA * 4)   // 139264 bytes

__global__ __launch_bounds__(256, 1)
void gemm_wmma(const float* __restrict__ x, const float* __restrict__ W,
               int M, int N) {
    extern __shared__ float smem[];
    float* As = smem;               // [128][LDA]
    float* Bs = smem + 128 * LDA;   // [128][LDA]

    const int tid = threadIdx.x;
    const int wid = tid >> 5;
    const long long m0 = (long long)blockIdx.x * 128;

    #pragma unroll
    for (int it = 0; it < 16; it++) {
        int idx = tid + it * 256;
        int row = idx >> 5;
        int kq  = idx & 31;
        long long gm = m0 + row; if (gm >= M) gm = M - 1;
        float4 v = __ldcs((const float4*)(x + gm * C_DIM + kq * 4));
        v.x = wmma::__float_to_tf32(v.x); v.y = wmma::__float_to_tf32(v.y);
        v.z = wmma::__float_to_tf32(v.z); v.w = wmma::__float_to_tf32(v.w);
        *(float4*)(As + row * LDA + kq * 4) = v;
    }
    #pragma unroll
    for (int it = 0; it < 16; it++) {
        int idx = tid + it * 256;
        int row = idx >> 5;
        int kq  = idx & 31;
        float4 v = *(const float4*)(W + row * C_DIM + kq * 4);
        v.x = wmma::__float_to_tf32(v.x); v.y = wmma::__float_to_tf32(v.y);
        v.z = wmma::__float_to_tf32(v.z); v.w = wmma::__float_to_tf32(v.w);
        *(float4*)(Bs + row * LDA + kq * 4) = v;
    }
    __syncthreads();

    const int wm = wid & 1;
    const int wn = wid >> 1;

    wmma::fragment<wmma::accumulator, 16, 16, 8, float> acc[4][2];
    #pragma unroll
    for (int i = 0; i < 4; i++)
        #pragma unroll
        for (int j = 0; j < 2; j++) wmma::fill_fragment(acc[i][j], 0.0f);

    #pragma unroll
    for (int ks = 0; ks < 16; ks++) {
        const int k = ks * 8;
        wmma::fragment<wmma::matrix_a, 16, 16, 8, wmma::precision::tf32,
                       wmma::row_major> a[4];
        wmma::fragment<wmma::matrix_b, 16, 16, 8, wmma::precision::tf32,
                       wmma::col_major> b[2];
        #pragma unroll
        for (int i = 0; i < 4; i++)
            wmma::load_matrix_sync(a[i], As + (wm * 64 + i * 16) * LDA + k, LDA);
        #pragma unroll
        for (int j = 0; j < 2; j++)
            wmma::load_matrix_sync(b[j], Bs + (wn * 32 + j * 16) * LDA + k, LDA);
        #pragma unroll
        for (int i = 0; i < 4; i++)
            #pragma unroll
            for (int j = 0; j < 2; j++)
                wmma::mma_sync(acc[i][j], a[i], b[j], acc[i][j]);
    }

    // Epilogue: frags -> smem -> fp16 node-major z (write-back: wants L2).
    __syncthreads();
    float* Os = smem;
    #pragma unroll
    for (int i = 0; i < 4; i++)
        #pragma unroll
        for (int j = 0; j < 2; j++)
            wmma::store_matrix_sync(
                Os + (wm * 64 + i * 16) * LDO + wn * 32 + j * 16,
                acc[i][j], LDO, wmma::mem_row_major);
    __syncthreads();

    #pragma unroll
    for (int it = 0; it < 16; it++) {
        int idx = tid + it * 256;
        int row = idx >> 5;
        int q   = idx & 31;
        long long gm = m0 + row;
        if (gm < M) {
            float4 v = *(const float4*)(Os + row * LDO + q * 4);
            __half2 h0 = __floats2half2_rn(v.x, v.y);
            __half2 h1 = __floats2half2_rn(v.z, v.w);
            int b = (int)(gm / N);
            int n = (int)(gm % N);
            uint2 pack;
            pack.x = *(uint32_t*)&h0;
            pack.y = *(uint32_t*)&h1;
            g_zh[(size_t)n * 128 + b * 32 + q] = pack;
        }
    }
}

// ===========================================================================
// CSR build
// ===========================================================================
__global__ void k_zero_cnt(int n) {
    int i = blockIdx.x * blockDim.x + threadIdx.x;
    if (i < n) g_cnt[i] = 0;
}

__global__ void k_count(const int* __restrict__ rows, int E) {
    int e = blockIdx.x * blockDim.x + threadIdx.x;
    if (e < E) atomicAdd(&g_cnt[rows[e]], 1);
}

#define SCAN_T 1024
__global__ __launch_bounds__(SCAN_T)
void k_scan(int n, int E) {
    __shared__ int s[SCAN_T];
    const int t = threadIdx.x;
    const int chunk = (n + SCAN_T - 1) / SCAN_T;
    const int base = t * chunk;
    int sum = 0;
    for (int j = 0; j < chunk; j++) {
        int r = base + j;
        if (r < n) sum += g_cnt[r];
    }
    s[t] = sum;
    __syncthreads();
    #pragma unroll
    for (int d = 1; d < SCAN_T; d <<= 1) {
        int v = (t >= d) ? s[t - d] : 0;
        __syncthreads();
        s[t] += v;
        __syncthreads();
    }
    int run = s[t] - sum;
    for (int j = 0; j < chunk; j++) {
        int r = base + j;
        if (r < n) {
            g_rowptr[r] = run;
            g_ofs[r]    = run;
            run += g_cnt[r];
        }
    }
    if (t == 0) g_rowptr[n] = E;
}

__global__ void k_fill(const int* __restrict__ rows, const int* __restrict__ cols,
                       const float* __restrict__ vals, int E) {
    int e = blockIdx.x * blockDim.x + threadIdx.x;
    if (e >= E) return;
    int r = rows[e];
    int pos = atomicAdd(&g_ofs[r], 1);
    float2 ed;
    ed.x = __int_as_float(cols[e]);
    ed.y = vals[e];
    g_edata[pos] = ed;
}

// ===========================================================================
// Gather: 2 warps per row; warp covers 2 batches (contiguous 512B per edge).
// 2-way unrolled edge loop, fp32 accumulate, bias fused, streaming stores.
// ===========================================================================
__device__ __forceinline__ void accum_pair(const uint2* __restrict__ src,
                                           int lane, float v,
                                           float4& a0, float4& a1) {
    uint2 p0 = __ldg(src + lane);
    uint2 p1 = __ldg(src + lane + 32);
    float2 fa, fb;
    fa = __half22float2(*(__half2*)&p0.x); fb = __half22float2(*(__half2*)&p0.y);
    a0.x = fmaf(v, fa.x, a0.x); a0.y = fmaf(v, fa.y, a0.y);
    a0.z = fmaf(v, fb.x, a0.z); a0.w = fmaf(v, fb.y, a0.w);
    fa = __half22float2(*(__half2*)&p1.x); fb = __half22float2(*(__half2*)&p1.y);
    a1.x = fmaf(v, fa.x, a1.x); a1.y = fmaf(v, fa.y, a1.y);
    a1.z = fmaf(v, fb.x, a1.z); a1.w = fmaf(v, fb.y, a1.w);
}

__global__ __launch_bounds__(256)
void k_gather(const float* __restrict__ bias, float* __restrict__ out, int N) {
    int gw   = (blockIdx.x * blockDim.x + threadIdx.x) >> 5;
    int lane = threadIdx.x & 31;
    int r    = gw >> 1;
    int half = gw & 1;          // 0: batches {0,1}, 1: batches {2,3}
    if (r >= N) return;
    const int boff = half * 64; // uint2 offset into node block

    float4 acc0 = make_float4(0.f, 0.f, 0.f, 0.f);
    float4 acc1 = acc0, bcc0 = acc0, bcc1 = acc0;

    const int start = g_rowptr[r];
    const int end   = g_rowptr[r + 1];

    int i = start;
    for (; i + 2 <= end; i += 2) {
        float2 e0 = __ldg(&g_edata[i]);
        float2 e1 = __ldg(&g_edata[i + 1]);
        const uint2* s0 = g_zh + (size_t)__float_as_int(e0.x) * 128 + boff;
        const uint2* s1 = g_zh + (size_t)__float_as_int(e1.x) * 128 + boff;
        accum_pair(s0, lane, e0.y, acc0, acc1);
        accum_pair(s1, lane, e1.y, bcc0, bcc1);
    }
    if (i < end) {
        float2 e0 = __ldg(&g_edata[i]);
        const uint2* s0 = g_zh + (size_t)__float_as_int(e0.x) * 128 + boff;
        accum_pair(s0, lane, e0.y, acc0, acc1);
    }

    float4 bv = ((const float4*)bias)[lane];
    acc0.x += bcc0.x + bv.x; acc0.y += bcc0.y + bv.y;
    acc0.z += bcc0.z + bv.z; acc0.w += bcc0.w + bv.w;
    acc1.x += bcc1.x + bv.x; acc1.y += bcc1.y + bv.y;
    acc1.z += bcc1.z + bv.z; acc1.w += bcc1.w + bv.w;

    const size_t NB = (size_t)N * 32;   // float4 units per batch
    float4* dst = (float4*)out + (size_t)(half * 2) * NB + (size_t)r * 32 + lane;
    __stcs(dst,      acc0);
    __stcs(dst + NB, acc1);
}

// ===========================================================================
extern "C" void kernel_launch(void* const* d_in, const int* in_sizes, int n_in,
                              void* d_out, int out_size) {
    const float* x    = (const float*)d_in[0];
    const int*   adj  = (const int*)d_in[1];
    const float* vals = (const float*)d_in[2];
    const float* W    = (const float*)d_in[3];
    const float* bias = (const float*)d_in[4];
    float* out = (float*)d_out;

    const int E = in_sizes[2];
    const int N = in_sizes[0] / (B_DIM * C_DIM);
    const int M = B_DIM * N;

    const int* rows = adj;
    const int* cols = adj + E;

    static cudaStream_t s2 = nullptr;
    static cudaEvent_t evFork, evJoin;
    if (!s2) {
        cudaStreamCreateWithFlags(&s2, cudaStreamNonBlocking);
        cudaEventCreateWithFlags(&evFork, cudaEventDisableTiming);
        cudaEventCreateWithFlags(&evJoin, cudaEventDisableTiming);
        cudaFuncSetAttribute(gemm_wmma,
                             cudaFuncAttributeMaxDynamicSharedMemorySize, GEMM_SMEM);
    }

    // Fork: CSR build on s2 runs concurrently with GEMM on the main stream.
    cudaEventRecord(evFork, 0);
    cudaStreamWaitEvent(s2, evFork, 0);

    k_zero_cnt<<<(N + 255) / 256, 256, 0, s2>>>(N);
    k_count<<<(E + 255) / 256, 256, 0, s2>>>(rows, E);
    k_scan<<<1, SCAN_T, 0, s2>>>(N, E);
    k_fill<<<(E + 255) / 256, 256, 0, s2>>>(rows, cols, vals, E);
    cudaEventRecord(evJoin, s2);

    // GEMM
    int gtiles = (M + 127) / 128;
    gemm_wmma<<<gtiles, 256, GEMM_SMEM>>>(x, W, M, N);

    // Join: gather needs both CSR and z.
    cudaStreamWaitEvent(0, evJoin, 0);
    int blocks = (N * 64 + 255) / 256;
    k_gather<<<blocks, 256>>>(bias, out, N);
}